// round 9
// baseline (speedup 1.0000x reference)
#include <cuda_runtime.h>
#include <cuda_bf16.h>
#include <cstdint>
#include <math.h>

// ---------------- problem constants ----------------
#define TT   50
#define BB   2048
#define SST  256      // STATE
#define AAC  32       // ACTION
#define BEL  1024     // BELIEF
#define HID  1024     // HIDDEN
#define EMB  1024     // EMBED
#define KSA2 288      // STATE+ACTION (exact, 9 * 32)

// ================= scratch (device globals; no allocation allowed) =================
// bf16 hi/lo weight copies (converted once per launch)
__device__ __align__(16) __nv_bfloat16 g_Wsa_h[1024 * KSA2], g_Wsa_l[1024 * KSA2];
__device__ __align__(16) __nv_bfloat16 g_Wih_h[3072 * 1024], g_Wih_l[3072 * 1024];
__device__ __align__(16) __nv_bfloat16 g_Whh_h[3072 * 1024], g_Whh_l[3072 * 1024];
__device__ __align__(16) __nv_bfloat16 g_Wpb_h[1024 * 1024], g_Wpb_l[1024 * 1024];
__device__ __align__(16) __nv_bfloat16 g_Wps_h[512 * 1024],  g_Wps_l[512 * 1024];
__device__ __align__(16) __nv_bfloat16 g_Wqb_h[1024 * 2048], g_Wqb_l[1024 * 2048];
__device__ __align__(16) __nv_bfloat16 g_Wqs_h[512 * 1024],  g_Wqs_l[512 * 1024];
// pre-converted inputs (whole sequence, once per replay)
__device__ __align__(16) __nv_bfloat16 g_act_h[TT * BB * AAC], g_act_l[TT * BB * AAC];
__device__ __align__(16) __nv_bfloat16 g_obs_h[TT * BB * EMB], g_obs_l[TT * BB * EMB];
// bf16 hi/lo recurrent activations
__device__ __align__(16) __nv_bfloat16 g_st_h[BB * SST],  g_st_l[BB * SST];
__device__ __align__(16) __nv_bfloat16 g_rnn_h[BB * BEL], g_rnn_l[BB * BEL];
__device__ __align__(16) __nv_bfloat16 g_bel_h[BB * BEL], g_bel_l[BB * BEL];
__device__ __align__(16) __nv_bfloat16 g_ph_h[BB * HID],  g_ph_l[BB * HID];
__device__ __align__(16) __nv_bfloat16 g_qh_h[BB * HID],  g_qh_l[BB * HID];
// fp32 scratch
__device__ __align__(16) float g_gi[BB * 3 * BEL];
__device__ __align__(16) float g_gh[BB * 3 * BEL];
__device__ __align__(16) float g_pout[BB * 2 * SST];
__device__ __align__(16) float g_qout[BB * 2 * SST];

// ================= low-level helpers (sm_80-baseline PTX only) =================
__device__ __forceinline__ uint32_t smem_u32(const void* p) {
    uint32_t a;
    asm("{ .reg .u64 t; cvta.to.shared.u64 t, %1; cvt.u32.u64 %0, t; }" : "=r"(a) : "l"(p));
    return a;
}
__device__ __forceinline__ void cp16(uint32_t dst, const void* src) {
    asm volatile("cp.async.cg.shared.global [%0], [%1], 16;" :: "r"(dst), "l"(src));
}
#define CP_COMMIT()  asm volatile("cp.async.commit_group;" ::: "memory")
#define CP_WAIT1()   asm volatile("cp.async.wait_group 1;" ::: "memory")

__device__ __forceinline__ void ldsm4(uint32_t* r, uint32_t addr) {
    asm volatile("ldmatrix.sync.aligned.m8n8.x4.shared.b16 {%0,%1,%2,%3}, [%4];"
                 : "=r"(r[0]), "=r"(r[1]), "=r"(r[2]), "=r"(r[3]) : "r"(addr));
}
__device__ __forceinline__ void mma16816(float* c, const uint32_t* a, uint32_t b0, uint32_t b1) {
    asm volatile(
        "mma.sync.aligned.m16n8k16.row.col.f32.bf16.bf16.f32 "
        "{%0,%1,%2,%3}, {%4,%5,%6,%7}, {%8,%9}, {%0,%1,%2,%3};"
        : "+f"(c[0]), "+f"(c[1]), "+f"(c[2]), "+f"(c[3])
        : "r"(a[0]), "r"(a[1]), "r"(a[2]), "r"(a[3]), "r"(b0), "r"(b1));
}

// ================= GEMM parameter block (per grid.z) =================
struct GArg {
    const __nv_bfloat16 *A0h, *A0l;   // A source 0 (cols [0, K0))
    const __nv_bfloat16 *A1h, *A1l;   // A source 1 (cols [K0, K)) or null
    int lda0, lda1, K0, K;
    const __nv_bfloat16 *Wh, *Wl;     // W [N, K] row-major
    int ldw;
    const float* bias;
    float* C;                          // fp32 out (if !BF16OUT)
    __nv_bfloat16 *Ch, *Cl;           // bf16 hi/lo out (if BF16OUT)
    int N;
};

// ================= warp-MMA split-bf16 GEMM =================
// C[2048, N] = act( [A0|A1] @ W^T + bias ), 3-term split bf16 (Ah*Wh + Ah*Wl + Al*Wh).
// CTA tile 128x128, 8 warps (4M x 2N), warp tile 32x64, BK=32, 2-stage cp.async,
// 2 CTAs/SM. grid.z selects one of two GArg blocks (batched independent GEMMs).
#define LDSW    40                       // smem row stride in bf16 (32 + 8 pad)
#define TSB     (128 * LDSW * 2)         // tile bytes (10240)
#define STAGE_B (4u * TSB)               // Ah, Al, Wh, Wl (40960 B)
#define SMEM_SZ (2u * STAGE_B)           // 81920 B -> 2 CTAs/SM

__device__ __forceinline__ void load_stage(uint32_t sbase, const GArg& g,
                                           int row0, int col0, int kk, int tid)
{
    // resolve A source for this 32-wide chunk (K0 % 32 == 0 guaranteed)
    const __nv_bfloat16 *ah, *al; int la, ko;
    if (kk < g.K0) { ah = g.A0h; al = g.A0l; la = g.lda0; ko = kk; }
    else           { ah = g.A1h; al = g.A1l; la = g.lda1; ko = kk - g.K0; }

    const int r  = tid >> 2;          // 0..63 (rows, x2 iters)
    const int c4 = tid & 3;           // 16B chunk within 32 cols
#pragma unroll
    for (int i = 0; i < 2; i++) {
        const int rr = i * 64 + r;
        const uint32_t so = (uint32_t)(rr * (LDSW * 2) + c4 * 16);
        cp16(sbase + so,            ah + (size_t)(row0 + rr) * la + ko + c4 * 8);
        cp16(sbase + TSB + so,      al + (size_t)(row0 + rr) * la + ko + c4 * 8);
        cp16(sbase + 2 * TSB + so,  g.Wh + (size_t)(col0 + rr) * g.ldw + kk + c4 * 8);
        cp16(sbase + 3 * TSB + so,  g.Wl + (size_t)(col0 + rr) * g.ldw + kk + c4 * 8);
    }
}

template <bool RELU, bool BF16OUT>
__global__ __launch_bounds__(256, 2)
void mma_gemm2(GArg ga, GArg gb)
{
    const GArg g = (blockIdx.z == 0) ? ga : gb;

    extern __shared__ char smem_raw[];
    const uint32_t sb0 = smem_u32(smem_raw);

    const int tid = threadIdx.x;
    const int lane = tid & 31, wid = tid >> 5;
    const int wm = wid & 3, wn = wid >> 2;          // 4 x 2 warp grid
    const int row0 = blockIdx.y * 128, col0 = blockIdx.x * 128;

    float acc[2][8][4];
#pragma unroll
    for (int a = 0; a < 2; a++)
#pragma unroll
        for (int b = 0; b < 8; b++)
#pragma unroll
            for (int c = 0; c < 4; c++) acc[a][b][c] = 0.0f;

    const int NC = g.K / 32;
    load_stage(sb0, g, row0, col0, 0, tid); CP_COMMIT();

    const int lrow = lane & 15;
    const int lcol = (lane >> 4) << 3;

    for (int c = 0; c < NC; c++) {
        // issue next stage, then wait for current
        if (c + 1 < NC)
            load_stage(sb0 + (uint32_t)((c + 1) & 1) * STAGE_B, g, row0, col0, (c + 1) * 32, tid);
        CP_COMMIT();
        CP_WAIT1();
        __syncthreads();

        const uint32_t st = sb0 + (uint32_t)(c & 1) * STAGE_B;
#pragma unroll
        for (int k16 = 0; k16 < 32; k16 += 16) {
            uint32_t ah[2][4], al[2][4];
#pragma unroll
            for (int mt = 0; mt < 2; mt++) {
                uint32_t ra = (uint32_t)((wm * 32 + mt * 16 + lrow) * LDSW + k16 + lcol) * 2;
                ldsm4(ah[mt], st + ra);
                ldsm4(al[mt], st + TSB + ra);
            }
#pragma unroll
            for (int gg = 0; gg < 4; gg++) {
                uint32_t wh[4], wl[4];
                uint32_t rb = (uint32_t)((wn * 64 + gg * 16 + lrow) * LDSW + k16 + lcol) * 2;
                ldsm4(wh, st + 2 * TSB + rb);
                ldsm4(wl, st + 3 * TSB + rb);
#pragma unroll
                for (int mt = 0; mt < 2; mt++)
#pragma unroll
                    for (int h = 0; h < 2; h++) {
                        float* cc = acc[mt][gg * 2 + h];
                        mma16816(cc, ah[mt], wh[h], wh[h + 2]);
                        mma16816(cc, ah[mt], wl[h], wl[h + 2]);
                        mma16816(cc, al[mt], wh[h], wh[h + 2]);
                    }
            }
        }
        __syncthreads();   // all warps done with stage (c&1) before it is reloaded
    }

    // ---- epilogue ----
    const int gid = lane >> 2, tig = lane & 3;
#pragma unroll
    for (int mt = 0; mt < 2; mt++) {
        const int ra = row0 + wm * 32 + mt * 16 + gid;
#pragma unroll
        for (int nt = 0; nt < 8; nt++) {
            const int col = col0 + wn * 64 + nt * 8 + tig * 2;
            const float b0 = g.bias[col], b1 = g.bias[col + 1];
            const float* cc = acc[mt][nt];
#pragma unroll
            for (int half = 0; half < 2; half++) {
                const int r = ra + half * 8;
                float v0 = cc[half * 2 + 0] + b0;
                float v1 = cc[half * 2 + 1] + b1;
                if (RELU) { v0 = fmaxf(v0, 0.0f); v1 = fmaxf(v1, 0.0f); }
                const size_t o = (size_t)r * g.N + col;
                if (BF16OUT) {
                    __nv_bfloat16 h0 = __float2bfloat16(v0);
                    __nv_bfloat16 h1 = __float2bfloat16(v1);
                    g.Ch[o] = h0; g.Ch[o + 1] = h1;
                    g.Cl[o]     = __float2bfloat16(v0 - __bfloat162float(h0));
                    g.Cl[o + 1] = __float2bfloat16(v1 - __bfloat162float(h1));
                } else {
                    g.C[o] = v0; g.C[o + 1] = v1;
                }
            }
        }
    }
}

// ================= elementwise kernels =================
__device__ __forceinline__ void bf_split(float x, __nv_bfloat16& h, __nv_bfloat16& l) {
    h = __float2bfloat16(x);
    l = __float2bfloat16(x - __bfloat162float(h));
}

__global__ void conv_split(const float* __restrict__ src,
                           __nv_bfloat16* __restrict__ hi, __nv_bfloat16* __restrict__ lo,
                           int total)
{
    int i = blockIdx.x * blockDim.x + threadIdx.x;
    if (i >= total) return;
    float x = src[i];
    __nv_bfloat16 h, l; bf_split(x, h, l);
    hi[i] = h; lo[i] = l;
}

__global__ void gru_combine(const float* __restrict__ gi, const float* __restrict__ gh,
                            const float* __restrict__ hprev, float* __restrict__ hout,
                            __nv_bfloat16* __restrict__ bel_h, __nv_bfloat16* __restrict__ bel_l)
{
    int i = blockIdx.x * blockDim.x + threadIdx.x;
    if (i >= BB * BEL) return;
    int b = i >> 10, c = i & 1023;
    const float* gib = gi + (size_t)b * 3 * BEL;
    const float* ghb = gh + (size_t)b * 3 * BEL;
    float ir = gib[c],           hr = ghb[c];
    float iz = gib[BEL + c],     hz = ghb[BEL + c];
    float in = gib[2 * BEL + c], hn = ghb[2 * BEL + c];
    float r = 1.0f / (1.0f + expf(-(ir + hr)));
    float z = 1.0f / (1.0f + expf(-(iz + hz)));
    float n = tanhf(in + r * hn);
    float h = (1.0f - z) * n + z * hprev[i];
    hout[i] = h;
    __nv_bfloat16 bh, bl; bf_split(h, bh, bl);
    bel_h[i] = bh; bel_l[i] = bl;
}

// both heads fused; q-half also emits next-step state (bf16 hi/lo)
__global__ void head_epi2(const float* __restrict__ pout, const float* __restrict__ qout,
                          const float* __restrict__ pn, const float* __restrict__ qn,
                          float* __restrict__ o_ps, float* __restrict__ o_pm, float* __restrict__ o_pstd,
                          float* __restrict__ o_qs, float* __restrict__ o_qm, float* __restrict__ o_qstd,
                          __nv_bfloat16* __restrict__ st_h, __nv_bfloat16* __restrict__ st_l)
{
    int i = blockIdx.x * blockDim.x + threadIdx.x;
    if (i >= 2 * BB * SST) return;
    const bool isq = i >= BB * SST;
    const int j = isq ? i - BB * SST : i;
    const int b = j >> 8, c = j & 255;
    const float* src = isq ? qout : pout;
    float m  = src[(size_t)b * 2 * SST + c];
    float lg = src[(size_t)b * 2 * SST + SST + c];
    float y  = expf(lg);
    float sp = (y > 20.0f) ? y : log1pf(expf(y));
    float sd = sp + 0.1f;
    float ns = isq ? qn[j] : pn[j];
    float stv = m + sd * ns;
    if (isq) {
        o_qm[j] = m; o_qstd[j] = sd; o_qs[j] = stv;
        __nv_bfloat16 h, l; bf_split(stv, h, l);
        st_h[j] = h; st_l[j] = l;
    } else {
        o_pm[j] = m; o_pstd[j] = sd; o_ps[j] = stv;
    }
}

// ================= host dispatch =================
static inline GArg mk(const __nv_bfloat16* A0h, const __nv_bfloat16* A0l, int lda0, int K0,
                      const __nv_bfloat16* A1h, const __nv_bfloat16* A1l, int lda1, int K,
                      const __nv_bfloat16* Wh, const __nv_bfloat16* Wl, int ldw,
                      const float* bias, int N,
                      float* C, __nv_bfloat16* Ch, __nv_bfloat16* Cl)
{
    GArg g;
    g.A0h = A0h; g.A0l = A0l; g.A1h = A1h; g.A1l = A1l;
    g.lda0 = lda0; g.lda1 = lda1; g.K0 = K0; g.K = K;
    g.Wh = Wh; g.Wl = Wl; g.ldw = ldw; g.bias = bias;
    g.C = C; g.Ch = Ch; g.Cl = Cl; g.N = N;
    return g;
}

extern "C" void kernel_launch(void* const* d_in, const int* in_sizes, int n_in,
                              void* d_out, int out_size)
{
    const float* prev_state   = (const float*)d_in[0];
    const float* actions      = (const float*)d_in[1];
    const float* prev_belief  = (const float*)d_in[2];
    const float* observations = (const float*)d_in[3];
    const float* prior_noise  = (const float*)d_in[4];
    const float* post_noise   = (const float*)d_in[5];
    const float* W_sa = (const float*)d_in[6];
    const float* b_sa = (const float*)d_in[7];
    const float* W_ih = (const float*)d_in[8];
    const float* W_hh = (const float*)d_in[9];
    const float* b_ih = (const float*)d_in[10];
    const float* b_hh = (const float*)d_in[11];
    const float* W_pb = (const float*)d_in[12];
    const float* b_pb = (const float*)d_in[13];
    const float* W_ps = (const float*)d_in[14];
    const float* b_ps = (const float*)d_in[15];
    const float* W_qb = (const float*)d_in[16];
    const float* b_qb = (const float*)d_in[17];
    const float* W_qs = (const float*)d_in[18];
    const float* b_qs = (const float*)d_in[19];

    float* out = (float*)d_out;
    float* out_bel  = out;
    float* out_ps   = out_bel  + (size_t)TT * BB * BEL;
    float* out_pm   = out_ps   + (size_t)TT * BB * SST;
    float* out_pstd = out_pm   + (size_t)TT * BB * SST;
    float* out_qs   = out_pstd + (size_t)TT * BB * SST;
    float* out_qm   = out_qs   + (size_t)TT * BB * SST;
    float* out_qstd = out_qm   + (size_t)TT * BB * SST;

    cudaFuncSetAttribute(mma_gemm2<true, true>,   cudaFuncAttributeMaxDynamicSharedMemorySize, SMEM_SZ);
    cudaFuncSetAttribute(mma_gemm2<false, false>, cudaFuncAttributeMaxDynamicSharedMemorySize, SMEM_SZ);

    __nv_bfloat16 *Wsa_h, *Wsa_l, *Wih_h, *Wih_l, *Whh_h, *Whh_l, *Wpb_h, *Wpb_l,
                  *Wps_h, *Wps_l, *Wqb_h, *Wqb_l, *Wqs_h, *Wqs_l,
                  *act_h, *act_l, *obs_h, *obs_l, *st_h, *st_l,
                  *rnn_h, *rnn_l, *bel_h, *bel_l, *ph_h, *ph_l, *qh_h, *qh_l;
    float *gi, *gh, *pout, *qout;
    cudaGetSymbolAddress((void**)&Wsa_h, g_Wsa_h); cudaGetSymbolAddress((void**)&Wsa_l, g_Wsa_l);
    cudaGetSymbolAddress((void**)&Wih_h, g_Wih_h); cudaGetSymbolAddress((void**)&Wih_l, g_Wih_l);
    cudaGetSymbolAddress((void**)&Whh_h, g_Whh_h); cudaGetSymbolAddress((void**)&Whh_l, g_Whh_l);
    cudaGetSymbolAddress((void**)&Wpb_h, g_Wpb_h); cudaGetSymbolAddress((void**)&Wpb_l, g_Wpb_l);
    cudaGetSymbolAddress((void**)&Wps_h, g_Wps_h); cudaGetSymbolAddress((void**)&Wps_l, g_Wps_l);
    cudaGetSymbolAddress((void**)&Wqb_h, g_Wqb_h); cudaGetSymbolAddress((void**)&Wqb_l, g_Wqb_l);
    cudaGetSymbolAddress((void**)&Wqs_h, g_Wqs_h); cudaGetSymbolAddress((void**)&Wqs_l, g_Wqs_l);
    cudaGetSymbolAddress((void**)&act_h, g_act_h); cudaGetSymbolAddress((void**)&act_l, g_act_l);
    cudaGetSymbolAddress((void**)&obs_h, g_obs_h); cudaGetSymbolAddress((void**)&obs_l, g_obs_l);
    cudaGetSymbolAddress((void**)&st_h,  g_st_h);  cudaGetSymbolAddress((void**)&st_l,  g_st_l);
    cudaGetSymbolAddress((void**)&rnn_h, g_rnn_h); cudaGetSymbolAddress((void**)&rnn_l, g_rnn_l);
    cudaGetSymbolAddress((void**)&bel_h, g_bel_h); cudaGetSymbolAddress((void**)&bel_l, g_bel_l);
    cudaGetSymbolAddress((void**)&ph_h,  g_ph_h);  cudaGetSymbolAddress((void**)&ph_l,  g_ph_l);
    cudaGetSymbolAddress((void**)&qh_h,  g_qh_h);  cudaGetSymbolAddress((void**)&qh_l,  g_qh_l);
    cudaGetSymbolAddress((void**)&gi,   g_gi);   cudaGetSymbolAddress((void**)&gh,   g_gh);
    cudaGetSymbolAddress((void**)&pout, g_pout); cudaGetSymbolAddress((void**)&qout, g_qout);

    // ---- one-time conversions (inside graph; replay-deterministic) ----
    auto conv = [](const float* s, __nv_bfloat16* h, __nv_bfloat16* l, int total) {
        conv_split<<<(total + 255) / 256, 256>>>(s, h, l, total);
    };
    conv(W_sa, Wsa_h, Wsa_l, 1024 * KSA2);
    conv(W_ih, Wih_h, Wih_l, 3072 * 1024);
    conv(W_hh, Whh_h, Whh_l, 3072 * 1024);
    conv(W_pb, Wpb_h, Wpb_l, 1024 * 1024);
    conv(W_ps, Wps_h, Wps_l,  512 * 1024);
    conv(W_qb, Wqb_h, Wqb_l, 1024 * 2048);
    conv(W_qs, Wqs_h, Wqs_l,  512 * 1024);
    conv(actions,      act_h, act_l, TT * BB * AAC);
    conv(observations, obs_h, obs_l, TT * BB * EMB);
    conv(prev_state,   st_h,  st_l,  BB * SST);
    conv(prev_belief,  bel_h, bel_l, BB * BEL);

    const dim3 g_sa(8, 16, 1), g_gate(24, 16, 2), g_pq(8, 16, 2), g_ss(4, 16, 2);
    const int nb_bel = (BB * BEL) / 256, nb_head2 = (2 * BB * SST) / 256;

    for (int t = 0; t < TT; t++) {
        const __nv_bfloat16* a_h = act_h + (size_t)t * BB * AAC;
        const __nv_bfloat16* a_l = act_l + (size_t)t * BB * AAC;
        const __nv_bfloat16* o_h = obs_h + (size_t)t * BB * EMB;
        const __nv_bfloat16* o_l = obs_l + (size_t)t * BB * EMB;
        const float* pn_t = prior_noise + (size_t)t * BB * SST;
        const float* qn_t = post_noise  + (size_t)t * BB * SST;
        const float* bel_prev_f32 = (t == 0) ? prev_belief
                                             : out_bel + (size_t)(t - 1) * BB * BEL;
        float* bel_t = out_bel + (size_t)t * BB * BEL;

        // 1. rnn_in = relu([state | action] @ W_sa^T + b_sa) -> bf16 pair
        {
            GArg a = mk(st_h, st_l, SST, SST, a_h, a_l, AAC, KSA2,
                        Wsa_h, Wsa_l, KSA2, b_sa, BEL, nullptr, rnn_h, rnn_l);
            mma_gemm2<true, true><<<g_sa, 256, SMEM_SZ>>>(a, a);
        }
        // 2. GRU gates, batched: z0 gi = rnn@W_ih^T, z1 gh = bel@W_hh^T
        {
            GArg a = mk(rnn_h, rnn_l, BEL, BEL, nullptr, nullptr, 0, BEL,
                        Wih_h, Wih_l, BEL, b_ih, 3 * BEL, gi, nullptr, nullptr);
            GArg b = mk(bel_h, bel_l, BEL, BEL, nullptr, nullptr, 0, BEL,
                        Whh_h, Whh_l, BEL, b_hh, 3 * BEL, gh, nullptr, nullptr);
            mma_gemm2<false, false><<<g_gate, 256, SMEM_SZ>>>(a, b);
        }
        gru_combine<<<nb_bel, 256>>>(gi, gh, bel_prev_f32, bel_t, bel_h, bel_l);

        // 3. hidden heads, batched: z0 ph = relu(bel@W_pb^T), z1 qh = relu([bel|obs]@W_qb^T)
        {
            GArg a = mk(bel_h, bel_l, BEL, BEL, nullptr, nullptr, 0, BEL,
                        Wpb_h, Wpb_l, BEL, b_pb, HID, nullptr, ph_h, ph_l);
            GArg b = mk(bel_h, bel_l, BEL, BEL, o_h, o_l, EMB, BEL + EMB,
                        Wqb_h, Wqb_l, BEL + EMB, b_qb, HID, nullptr, qh_h, qh_l);
            mma_gemm2<true, true><<<g_pq, 256, SMEM_SZ>>>(a, b);
        }
        // 4. stat heads, batched: z0 pout = ph@W_ps^T, z1 qout = qh@W_qs^T
        {
            GArg a = mk(ph_h, ph_l, HID, HID, nullptr, nullptr, 0, HID,
                        Wps_h, Wps_l, HID, b_ps, 2 * SST, pout, nullptr, nullptr);
            GArg b = mk(qh_h, qh_l, HID, HID, nullptr, nullptr, 0, HID,
                        Wqs_h, Wqs_l, HID, b_qs, 2 * SST, qout, nullptr, nullptr);
            mma_gemm2<false, false><<<g_ss, 256, SMEM_SZ>>>(a, b);
        }
        // 5. both head epilogues + next-step state
        head_epi2<<<nb_head2, 256>>>(pout, qout, pn_t, qn_t,
                                     out_ps   + (size_t)t * BB * SST,
                                     out_pm   + (size_t)t * BB * SST,
                                     out_pstd + (size_t)t * BB * SST,
                                     out_qs   + (size_t)t * BB * SST,
                                     out_qm   + (size_t)t * BB * SST,
                                     out_qstd + (size_t)t * BB * SST,
                                     st_h, st_l);
    }
}

// round 11
// speedup vs baseline: 1.4930x; 1.4930x over previous
#include <cuda_runtime.h>
#include <cuda_bf16.h>
#include <cstdint>
#include <math.h>

// ---------------- problem constants ----------------
#define TT   50
#define BB   2048
#define SST  256      // STATE
#define AAC  32       // ACTION
#define BEL  1024     // BELIEF
#define HID  1024     // HIDDEN
#define EMB  1024     // EMBED
#define KSA2 288      // STATE+ACTION (exact, 9 * 32)

// ================= scratch (device globals; no allocation allowed) =================
__device__ __align__(16) __nv_bfloat16 g_Wsa_h[1024 * KSA2], g_Wsa_l[1024 * KSA2];
__device__ __align__(16) __nv_bfloat16 g_Wih_h[3072 * 1024], g_Wih_l[3072 * 1024];
__device__ __align__(16) __nv_bfloat16 g_Whh_h[3072 * 1024], g_Whh_l[3072 * 1024];
__device__ __align__(16) __nv_bfloat16 g_Wpb_h[1024 * 1024], g_Wpb_l[1024 * 1024];
__device__ __align__(16) __nv_bfloat16 g_Wps_h[512 * 1024],  g_Wps_l[512 * 1024];
__device__ __align__(16) __nv_bfloat16 g_Wqb_h[1024 * 2048], g_Wqb_l[1024 * 2048];
__device__ __align__(16) __nv_bfloat16 g_Wqs_h[512 * 1024],  g_Wqs_l[512 * 1024];
// pre-converted inputs (whole sequence, once per replay)
__device__ __align__(16) __nv_bfloat16 g_act_h[TT * BB * AAC], g_act_l[TT * BB * AAC];
__device__ __align__(16) __nv_bfloat16 g_obs_h[TT * BB * EMB], g_obs_l[TT * BB * EMB];
// bf16 hi/lo recurrent activations
__device__ __align__(16) __nv_bfloat16 g_st_h[BB * SST],  g_st_l[BB * SST];
__device__ __align__(16) __nv_bfloat16 g_rnn_h[BB * BEL], g_rnn_l[BB * BEL];
__device__ __align__(16) __nv_bfloat16 g_bel_h[BB * BEL], g_bel_l[BB * BEL];
__device__ __align__(16) __nv_bfloat16 g_ph_h[BB * HID],  g_ph_l[BB * HID];
__device__ __align__(16) __nv_bfloat16 g_qh_h[BB * HID],  g_qh_l[BB * HID];
// fp32 scratch
__device__ __align__(16) float g_gi[BB * 3 * BEL];
__device__ __align__(16) float g_gh[BB * 3 * BEL];
__device__ __align__(16) float g_pout[BB * 2 * SST];
__device__ __align__(16) float g_qout[BB * 2 * SST];

// ================= low-level helpers (sm_80-baseline PTX only) =================
__device__ __forceinline__ uint32_t smem_u32(const void* p) {
    uint32_t a;
    asm("{ .reg .u64 t; cvta.to.shared.u64 t, %1; cvt.u32.u64 %0, t; }" : "=r"(a) : "l"(p));
    return a;
}
__device__ __forceinline__ void cp16(uint32_t dst, const void* src) {
    asm volatile("cp.async.cg.shared.global [%0], [%1], 16;" :: "r"(dst), "l"(src));
}
#define CP_COMMIT()  asm volatile("cp.async.commit_group;" ::: "memory")
#define CP_WAIT2()   asm volatile("cp.async.wait_group 2;" ::: "memory")

__device__ __forceinline__ void ldsm4(uint32_t* r, uint32_t addr) {
    asm volatile("ldmatrix.sync.aligned.m8n8.x4.shared.b16 {%0,%1,%2,%3}, [%4];"
                 : "=r"(r[0]), "=r"(r[1]), "=r"(r[2]), "=r"(r[3]) : "r"(addr));
}
__device__ __forceinline__ void mma16816(float* c, const uint32_t* a, uint32_t b0, uint32_t b1) {
    asm volatile(
        "mma.sync.aligned.m16n8k16.row.col.f32.bf16.bf16.f32 "
        "{%0,%1,%2,%3}, {%4,%5,%6,%7}, {%8,%9}, {%0,%1,%2,%3};"
        : "+f"(c[0]), "+f"(c[1]), "+f"(c[2]), "+f"(c[3])
        : "r"(a[0]), "r"(a[1]), "r"(a[2]), "r"(a[3]), "r"(b0), "r"(b1));
}

// ================= GEMM parameter block (per grid.z) =================
struct GArg {
    const __nv_bfloat16 *A0h, *A0l;   // A source 0 (cols [0, K0))
    const __nv_bfloat16 *A1h, *A1l;   // A source 1 (cols [K0, K)) or null
    int lda0, lda1, K0, K;
    const __nv_bfloat16 *Wh, *Wl;     // W [N, K] row-major
    int ldw;
    const float* bias;
    float* C;                          // fp32 out (if !BF16OUT)
    __nv_bfloat16 *Ch, *Cl;           // bf16 hi/lo out (if BF16OUT)
    int N;
};

// ================= warp-MMA split-bf16 GEMM =================
// C[2048, N] = act( [A0|A1] @ W^T + bias ), 3-term split bf16 (Ah*Wh + Ah*Wl + Al*Wh).
// CTA 128x128, 8 warps (4M x 2N), warp tile 32x64, BK=32, 4-stage cp.async, occ 1
// (full 255-reg budget: ~64 acc + fragments; occ-2 spills — R9 regression).
#define LDSW    40                       // smem row stride in bf16 (32 + 8 pad)
#define TSB     (128 * LDSW * 2)         // tile bytes (10240)
#define STAGE_B (4u * TSB)               // Ah, Al, Wh, Wl (40960 B)
#define NSTAGE  4
#define SMEM_SZ (NSTAGE * STAGE_B)       // 163840 B -> 1 CTA/SM

__device__ __forceinline__ void load_stage(uint32_t sbase, const GArg& g,
                                           int row0, int col0, int kk, int tid)
{
    // resolve A source for this 32-wide chunk (K0 % 32 == 0 guaranteed)
    const __nv_bfloat16 *ah, *al; int la, ko;
    if (kk < g.K0) { ah = g.A0h; al = g.A0l; la = g.lda0; ko = kk; }
    else           { ah = g.A1h; al = g.A1l; la = g.lda1; ko = kk - g.K0; }

    const int r  = tid >> 2;          // 0..63 (rows; x2 iters)
    const int c4 = tid & 3;           // 16B chunk within 32 cols
#pragma unroll
    for (int i = 0; i < 2; i++) {
        const int rr = i * 64 + r;
        const uint32_t so = (uint32_t)(rr * (LDSW * 2) + c4 * 16);
        cp16(sbase + so,            ah + (size_t)(row0 + rr) * la + ko + c4 * 8);
        cp16(sbase + TSB + so,      al + (size_t)(row0 + rr) * la + ko + c4 * 8);
        cp16(sbase + 2 * TSB + so,  g.Wh + (size_t)(col0 + rr) * g.ldw + kk + c4 * 8);
        cp16(sbase + 3 * TSB + so,  g.Wl + (size_t)(col0 + rr) * g.ldw + kk + c4 * 8);
    }
}

template <bool RELU, bool BF16OUT>
__global__ __launch_bounds__(256, 1)
void mma_gemm2(GArg ga, GArg gb)
{
    const GArg g = (blockIdx.z == 0) ? ga : gb;

    extern __shared__ char smem_raw[];
    const uint32_t sb0 = smem_u32(smem_raw);

    const int tid = threadIdx.x;
    const int lane = tid & 31, wid = tid >> 5;
    const int wm = wid & 3, wn = wid >> 2;          // 4 x 2 warp grid
    const int row0 = blockIdx.y * 128, col0 = blockIdx.x * 128;

    float acc[2][8][4];
#pragma unroll
    for (int a = 0; a < 2; a++)
#pragma unroll
        for (int b = 0; b < 8; b++)
#pragma unroll
            for (int c = 0; c < 4; c++) acc[a][b][c] = 0.0f;

    const int NC = g.K / 32;   // min K = 288 -> NC >= 9 > NSTAGE-1

    // prefetch stages 0..2
    load_stage(sb0,               g, row0, col0, 0,  tid); CP_COMMIT();
    load_stage(sb0 + STAGE_B,     g, row0, col0, 32, tid); CP_COMMIT();
    load_stage(sb0 + 2 * STAGE_B, g, row0, col0, 64, tid); CP_COMMIT();

    const int lrow = lane & 15;
    const int lcol = (lane >> 4) << 3;

    for (int c = 0; c < NC; c++) {
        CP_WAIT2();            // groups c+1, c+2 may remain in flight; c complete
        __syncthreads();

        // prefetch stage c+3 (its buffer was consumed at iter c-1; end-of-loop sync protects)
        const int pf = c + 3;
        if (pf < NC)
            load_stage(sb0 + (uint32_t)(pf & 3) * STAGE_B, g, row0, col0, pf * 32, tid);
        CP_COMMIT();

        const uint32_t st = sb0 + (uint32_t)(c & 3) * STAGE_B;
#pragma unroll
        for (int k16 = 0; k16 < 32; k16 += 16) {
            uint32_t ah[2][4], al[2][4], wh[4][4], wl[4][4];
#pragma unroll
            for (int mt = 0; mt < 2; mt++) {
                uint32_t ra = (uint32_t)((wm * 32 + mt * 16 + lrow) * LDSW + k16 + lcol) * 2;
                ldsm4(ah[mt], st + ra);
                ldsm4(al[mt], st + TSB + ra);
            }
#pragma unroll
            for (int gg = 0; gg < 4; gg++) {
                uint32_t rb = (uint32_t)((wn * 64 + gg * 16 + lrow) * LDSW + k16 + lcol) * 2;
                ldsm4(wh[gg], st + 2 * TSB + rb);
                ldsm4(wl[gg], st + 3 * TSB + rb);
            }
#pragma unroll
            for (int mt = 0; mt < 2; mt++)
#pragma unroll
                for (int gg = 0; gg < 4; gg++)
#pragma unroll
                    for (int h = 0; h < 2; h++) {
                        float* cc = acc[mt][gg * 2 + h];
                        mma16816(cc, ah[mt], wh[gg][h], wh[gg][h + 2]);
                        mma16816(cc, ah[mt], wl[gg][h], wl[gg][h + 2]);
                        mma16816(cc, al[mt], wh[gg][h], wh[gg][h + 2]);
                    }
        }
        __syncthreads();       // stage (c&3) free for reuse
    }

    // ---- epilogue ----
    const int gid = lane >> 2, tig = lane & 3;
#pragma unroll
    for (int mt = 0; mt < 2; mt++) {
        const int ra = row0 + wm * 32 + mt * 16 + gid;
#pragma unroll
        for (int nt = 0; nt < 8; nt++) {
            const int col = col0 + wn * 64 + nt * 8 + tig * 2;
            const float b0 = g.bias[col], b1 = g.bias[col + 1];
            const float* cc = acc[mt][nt];
#pragma unroll
            for (int half = 0; half < 2; half++) {
                const int r = ra + half * 8;
                float v0 = cc[half * 2 + 0] + b0;
                float v1 = cc[half * 2 + 1] + b1;
                if (RELU) { v0 = fmaxf(v0, 0.0f); v1 = fmaxf(v1, 0.0f); }
                const size_t o = (size_t)r * g.N + col;
                if (BF16OUT) {
                    __nv_bfloat16 h0 = __float2bfloat16(v0);
                    __nv_bfloat16 h1 = __float2bfloat16(v1);
                    g.Ch[o] = h0; g.Ch[o + 1] = h1;
                    g.Cl[o]     = __float2bfloat16(v0 - __bfloat162float(h0));
                    g.Cl[o + 1] = __float2bfloat16(v1 - __bfloat162float(h1));
                } else {
                    g.C[o] = v0; g.C[o + 1] = v1;
                }
            }
        }
    }
}

// ================= elementwise kernels =================
__device__ __forceinline__ void bf_split(float x, __nv_bfloat16& h, __nv_bfloat16& l) {
    h = __float2bfloat16(x);
    l = __float2bfloat16(x - __bfloat162float(h));
}

__global__ void conv_split(const float* __restrict__ src,
                           __nv_bfloat16* __restrict__ hi, __nv_bfloat16* __restrict__ lo,
                           int total)
{
    int i = blockIdx.x * blockDim.x + threadIdx.x;
    if (i >= total) return;
    float x = src[i];
    __nv_bfloat16 h, l; bf_split(x, h, l);
    hi[i] = h; lo[i] = l;
}

__global__ void gru_combine(const float* __restrict__ gi, const float* __restrict__ gh,
                            const float* __restrict__ hprev, float* __restrict__ hout,
                            __nv_bfloat16* __restrict__ bel_h, __nv_bfloat16* __restrict__ bel_l)
{
    int i = blockIdx.x * blockDim.x + threadIdx.x;
    if (i >= BB * BEL) return;
    int b = i >> 10, c = i & 1023;
    const float* gib = gi + (size_t)b * 3 * BEL;
    const float* ghb = gh + (size_t)b * 3 * BEL;
    float ir = gib[c],           hr = ghb[c];
    float iz = gib[BEL + c],     hz = ghb[BEL + c];
    float in = gib[2 * BEL + c], hn = ghb[2 * BEL + c];
    float r = 1.0f / (1.0f + expf(-(ir + hr)));
    float z = 1.0f / (1.0f + expf(-(iz + hz)));
    float n = tanhf(in + r * hn);
    float h = (1.0f - z) * n + z * hprev[i];
    hout[i] = h;
    __nv_bfloat16 bh, bl; bf_split(h, bh, bl);
    bel_h[i] = bh; bel_l[i] = bl;
}

// both heads fused; q-half also emits next-step state (bf16 hi/lo)
__global__ void head_epi2(const float* __restrict__ pout, const float* __restrict__ qout,
                          const float* __restrict__ pn, const float* __restrict__ qn,
                          float* __restrict__ o_ps, float* __restrict__ o_pm, float* __restrict__ o_pstd,
                          float* __restrict__ o_qs, float* __restrict__ o_qm, float* __restrict__ o_qstd,
                          __nv_bfloat16* __restrict__ st_h, __nv_bfloat16* __restrict__ st_l)
{
    int i = blockIdx.x * blockDim.x + threadIdx.x;
    if (i >= 2 * BB * SST) return;
    const bool isq = i >= BB * SST;
    const int j = isq ? i - BB * SST : i;
    const int b = j >> 8, c = j & 255;
    const float* src = isq ? qout : pout;
    float m  = src[(size_t)b * 2 * SST + c];
    float lg = src[(size_t)b * 2 * SST + SST + c];
    float y  = expf(lg);
    float sp = (y > 20.0f) ? y : log1pf(expf(y));
    float sd = sp + 0.1f;
    float ns = isq ? qn[j] : pn[j];
    float stv = m + sd * ns;
    if (isq) {
        o_qm[j] = m; o_qstd[j] = sd; o_qs[j] = stv;
        __nv_bfloat16 h, l; bf_split(stv, h, l);
        st_h[j] = h; st_l[j] = l;
    } else {
        o_pm[j] = m; o_pstd[j] = sd; o_ps[j] = stv;
    }
}

// ================= host dispatch =================
static inline GArg mk(const __nv_bfloat16* A0h, const __nv_bfloat16* A0l, int lda0, int K0,
                      const __nv_bfloat16* A1h, const __nv_bfloat16* A1l, int lda1, int K,
                      const __nv_bfloat16* Wh, const __nv_bfloat16* Wl, int ldw,
                      const float* bias, int N,
                      float* C, __nv_bfloat16* Ch, __nv_bfloat16* Cl)
{
    GArg g;
    g.A0h = A0h; g.A0l = A0l; g.A1h = A1h; g.A1l = A1l;
    g.lda0 = lda0; g.lda1 = lda1; g.K0 = K0; g.K = K;
    g.Wh = Wh; g.Wl = Wl; g.ldw = ldw; g.bias = bias;
    g.C = C; g.Ch = Ch; g.Cl = Cl; g.N = N;
    return g;
}

extern "C" void kernel_launch(void* const* d_in, const int* in_sizes, int n_in,
                              void* d_out, int out_size)
{
    const float* prev_state   = (const float*)d_in[0];
    const float* actions      = (const float*)d_in[1];
    const float* prev_belief  = (const float*)d_in[2];
    const float* observations = (const float*)d_in[3];
    const float* prior_noise  = (const float*)d_in[4];
    const float* post_noise   = (const float*)d_in[5];
    const float* W_sa = (const float*)d_in[6];
    const float* b_sa = (const float*)d_in[7];
    const float* W_ih = (const float*)d_in[8];
    const float* W_hh = (const float*)d_in[9];
    const float* b_ih = (const float*)d_in[10];
    const float* b_hh = (const float*)d_in[11];
    const float* W_pb = (const float*)d_in[12];
    const float* b_pb = (const float*)d_in[13];
    const float* W_ps = (const float*)d_in[14];
    const float* b_ps = (const float*)d_in[15];
    const float* W_qb = (const float*)d_in[16];
    const float* b_qb = (const float*)d_in[17];
    const float* W_qs = (const float*)d_in[18];
    const float* b_qs = (const float*)d_in[19];

    float* out = (float*)d_out;
    float* out_bel  = out;
    float* out_ps   = out_bel  + (size_t)TT * BB * BEL;
    float* out_pm   = out_ps   + (size_t)TT * BB * SST;
    float* out_pstd = out_pm   + (size_t)TT * BB * SST;
    float* out_qs   = out_pstd + (size_t)TT * BB * SST;
    float* out_qm   = out_qs   + (size_t)TT * BB * SST;
    float* out_qstd = out_qm   + (size_t)TT * BB * SST;

    cudaFuncSetAttribute(mma_gemm2<true, true>,   cudaFuncAttributeMaxDynamicSharedMemorySize, SMEM_SZ);
    cudaFuncSetAttribute(mma_gemm2<false, false>, cudaFuncAttributeMaxDynamicSharedMemorySize, SMEM_SZ);

    __nv_bfloat16 *Wsa_h, *Wsa_l, *Wih_h, *Wih_l, *Whh_h, *Whh_l, *Wpb_h, *Wpb_l,
                  *Wps_h, *Wps_l, *Wqb_h, *Wqb_l, *Wqs_h, *Wqs_l,
                  *act_h, *act_l, *obs_h, *obs_l, *st_h, *st_l,
                  *rnn_h, *rnn_l, *bel_h, *bel_l, *ph_h, *ph_l, *qh_h, *qh_l;
    float *gi, *gh, *pout, *qout;
    cudaGetSymbolAddress((void**)&Wsa_h, g_Wsa_h); cudaGetSymbolAddress((void**)&Wsa_l, g_Wsa_l);
    cudaGetSymbolAddress((void**)&Wih_h, g_Wih_h); cudaGetSymbolAddress((void**)&Wih_l, g_Wih_l);
    cudaGetSymbolAddress((void**)&Whh_h, g_Whh_h); cudaGetSymbolAddress((void**)&Whh_l, g_Whh_l);
    cudaGetSymbolAddress((void**)&Wpb_h, g_Wpb_h); cudaGetSymbolAddress((void**)&Wpb_l, g_Wpb_l);
    cudaGetSymbolAddress((void**)&Wps_h, g_Wps_h); cudaGetSymbolAddress((void**)&Wps_l, g_Wps_l);
    cudaGetSymbolAddress((void**)&Wqb_h, g_Wqb_h); cudaGetSymbolAddress((void**)&Wqb_l, g_Wqb_l);
    cudaGetSymbolAddress((void**)&Wqs_h, g_Wqs_h); cudaGetSymbolAddress((void**)&Wqs_l, g_Wqs_l);
    cudaGetSymbolAddress((void**)&act_h, g_act_h); cudaGetSymbolAddress((void**)&act_l, g_act_l);
    cudaGetSymbolAddress((void**)&obs_h, g_obs_h); cudaGetSymbolAddress((void**)&obs_l, g_obs_l);
    cudaGetSymbolAddress((void**)&st_h,  g_st_h);  cudaGetSymbolAddress((void**)&st_l,  g_st_l);
    cudaGetSymbolAddress((void**)&rnn_h, g_rnn_h); cudaGetSymbolAddress((void**)&rnn_l, g_rnn_l);
    cudaGetSymbolAddress((void**)&bel_h, g_bel_h); cudaGetSymbolAddress((void**)&bel_l, g_bel_l);
    cudaGetSymbolAddress((void**)&ph_h,  g_ph_h);  cudaGetSymbolAddress((void**)&ph_l,  g_ph_l);
    cudaGetSymbolAddress((void**)&qh_h,  g_qh_h);  cudaGetSymbolAddress((void**)&qh_l,  g_qh_l);
    cudaGetSymbolAddress((void**)&gi,   g_gi);   cudaGetSymbolAddress((void**)&gh,   g_gh);
    cudaGetSymbolAddress((void**)&pout, g_pout); cudaGetSymbolAddress((void**)&qout, g_qout);

    // ---- one-time conversions (inside graph; replay-deterministic) ----
    auto conv = [](const float* s, __nv_bfloat16* h, __nv_bfloat16* l, int total) {
        conv_split<<<(total + 255) / 256, 256>>>(s, h, l, total);
    };
    conv(W_sa, Wsa_h, Wsa_l, 1024 * KSA2);
    conv(W_ih, Wih_h, Wih_l, 3072 * 1024);
    conv(W_hh, Whh_h, Whh_l, 3072 * 1024);
    conv(W_pb, Wpb_h, Wpb_l, 1024 * 1024);
    conv(W_ps, Wps_h, Wps_l,  512 * 1024);
    conv(W_qb, Wqb_h, Wqb_l, 1024 * 2048);
    conv(W_qs, Wqs_h, Wqs_l,  512 * 1024);
    conv(actions,      act_h, act_l, TT * BB * AAC);
    conv(observations, obs_h, obs_l, TT * BB * EMB);
    conv(prev_state,   st_h,  st_l,  BB * SST);
    conv(prev_belief,  bel_h, bel_l, BB * BEL);

    const dim3 g_sa(8, 16, 1), g_gate(24, 16, 2), g_pq(8, 16, 2), g_ss(4, 16, 2);
    const int nb_bel = (BB * BEL) / 256, nb_head2 = (2 * BB * SST) / 256;

    for (int t = 0; t < TT; t++) {
        const __nv_bfloat16* a_h = act_h + (size_t)t * BB * AAC;
        const __nv_bfloat16* a_l = act_l + (size_t)t * BB * AAC;
        const __nv_bfloat16* o_h = obs_h + (size_t)t * BB * EMB;
        const __nv_bfloat16* o_l = obs_l + (size_t)t * BB * EMB;
        const float* pn_t = prior_noise + (size_t)t * BB * SST;
        const float* qn_t = post_noise  + (size_t)t * BB * SST;
        const float* bel_prev_f32 = (t == 0) ? prev_belief
                                             : out_bel + (size_t)(t - 1) * BB * BEL;
        float* bel_t = out_bel + (size_t)t * BB * BEL;

        // 1. rnn_in = relu([state | action] @ W_sa^T + b_sa) -> bf16 pair
        {
            GArg a = mk(st_h, st_l, SST, SST, a_h, a_l, AAC, KSA2,
                        Wsa_h, Wsa_l, KSA2, b_sa, BEL, nullptr, rnn_h, rnn_l);
            mma_gemm2<true, true><<<g_sa, 256, SMEM_SZ>>>(a, a);
        }
        // 2. GRU gates, batched: z0 gi = rnn@W_ih^T, z1 gh = bel@W_hh^T
        {
            GArg a = mk(rnn_h, rnn_l, BEL, BEL, nullptr, nullptr, 0, BEL,
                        Wih_h, Wih_l, BEL, b_ih, 3 * BEL, gi, nullptr, nullptr);
            GArg b = mk(bel_h, bel_l, BEL, BEL, nullptr, nullptr, 0, BEL,
                        Whh_h, Whh_l, BEL, b_hh, 3 * BEL, gh, nullptr, nullptr);
            mma_gemm2<false, false><<<g_gate, 256, SMEM_SZ>>>(a, b);
        }
        gru_combine<<<nb_bel, 256>>>(gi, gh, bel_prev_f32, bel_t, bel_h, bel_l);

        // 3. hidden heads, batched: z0 ph = relu(bel@W_pb^T), z1 qh = relu([bel|obs]@W_qb^T)
        {
            GArg a = mk(bel_h, bel_l, BEL, BEL, nullptr, nullptr, 0, BEL,
                        Wpb_h, Wpb_l, BEL, b_pb, HID, nullptr, ph_h, ph_l);
            GArg b = mk(bel_h, bel_l, BEL, BEL, o_h, o_l, EMB, BEL + EMB,
                        Wqb_h, Wqb_l, BEL + EMB, b_qb, HID, nullptr, qh_h, qh_l);
            mma_gemm2<true, true><<<g_pq, 256, SMEM_SZ>>>(a, b);
        }
        // 4. stat heads, batched: z0 pout = ph@W_ps^T, z1 qout = qh@W_qs^T
        {
            GArg a = mk(ph_h, ph_l, HID, HID, nullptr, nullptr, 0, HID,
                        Wps_h, Wps_l, HID, b_ps, 2 * SST, pout, nullptr, nullptr);
            GArg b = mk(qh_h, qh_l, HID, HID, nullptr, nullptr, 0, HID,
                        Wqs_h, Wqs_l, HID, b_qs, 2 * SST, qout, nullptr, nullptr);
            mma_gemm2<false, false><<<g_ss, 256, SMEM_SZ>>>(a, b);
        }
        // 5. both head epilogues + next-step state
        head_epi2<<<nb_head2, 256>>>(pout, qout, pn_t, qn_t,
                                     out_ps   + (size_t)t * BB * SST,
                                     out_pm   + (size_t)t * BB * SST,
                                     out_pstd + (size_t)t * BB * SST,
                                     out_qs   + (size_t)t * BB * SST,
                                     out_qm   + (size_t)t * BB * SST,
                                     out_qstd + (size_t)t * BB * SST,
                                     st_h, st_l);
    }
}

// round 12
// speedup vs baseline: 2.1327x; 1.4285x over previous
#include <cuda_runtime.h>
#include <cuda_fp16.h>
#include <cstdint>
#include <math.h>

// ---------------- problem constants ----------------
#define TT   50
#define BB   2048
#define SST  256      // STATE
#define AAC  32       // ACTION
#define BEL  1024     // BELIEF
#define HID  1024     // HIDDEN
#define EMB  1024     // EMBED
#define KSA2 288      // STATE+ACTION (exact, 9 * 32)

// ================= scratch (device globals; no allocation allowed) =================
// fp16 hi/lo weights (hi+lo gives ~22-bit effective mantissa)
__device__ __align__(16) __half g_Wsa_h[1024 * KSA2], g_Wsa_l[1024 * KSA2];
__device__ __align__(16) __half g_Wih_h[3072 * 1024], g_Wih_l[3072 * 1024];
__device__ __align__(16) __half g_Whh_h[3072 * 1024], g_Whh_l[3072 * 1024];
__device__ __align__(16) __half g_Wpb_h[1024 * 1024], g_Wpb_l[1024 * 1024];
__device__ __align__(16) __half g_Wps_h[512 * 1024],  g_Wps_l[512 * 1024];
__device__ __align__(16) __half g_Wqb_h[1024 * 2048], g_Wqb_l[1024 * 2048];
__device__ __align__(16) __half g_Wqs_h[512 * 1024],  g_Wqs_l[512 * 1024];
// fp16 activations (single precision: A-side error ~2^-12, dominates rel_err ~2e-4)
__device__ __align__(16) __half g_act[TT * BB * AAC];
__device__ __align__(16) __half g_obs[TT * BB * EMB];
__device__ __align__(16) __half g_st[BB * SST];
__device__ __align__(16) __half g_rnn[BB * BEL];
__device__ __align__(16) __half g_bel[BB * BEL];
__device__ __align__(16) __half g_ph[BB * HID];
__device__ __align__(16) __half g_qh[BB * HID];
// fp32 scratch
__device__ __align__(16) float g_gi[BB * 3 * BEL];
__device__ __align__(16) float g_gh[BB * 3 * BEL];
__device__ __align__(16) float g_pout[BB * 2 * SST];
__device__ __align__(16) float g_qout[BB * 2 * SST];

// ================= low-level helpers (sm_80-baseline PTX only) =================
__device__ __forceinline__ uint32_t smem_u32(const void* p) {
    uint32_t a;
    asm("{ .reg .u64 t; cvta.to.shared.u64 t, %1; cvt.u32.u64 %0, t; }" : "=r"(a) : "l"(p));
    return a;
}
__device__ __forceinline__ void cp16(uint32_t dst, const void* src) {
    asm volatile("cp.async.cg.shared.global [%0], [%1], 16;" :: "r"(dst), "l"(src));
}
#define CP_COMMIT()  asm volatile("cp.async.commit_group;" ::: "memory")
#define CP_WAIT3()   asm volatile("cp.async.wait_group 3;" ::: "memory")

__device__ __forceinline__ void ldsm4(uint32_t* r, uint32_t addr) {
    asm volatile("ldmatrix.sync.aligned.m8n8.x4.shared.b16 {%0,%1,%2,%3}, [%4];"
                 : "=r"(r[0]), "=r"(r[1]), "=r"(r[2]), "=r"(r[3]) : "r"(addr));
}
__device__ __forceinline__ void mma16816(float* c, const uint32_t* a, uint32_t b0, uint32_t b1) {
    asm volatile(
        "mma.sync.aligned.m16n8k16.row.col.f32.f16.f16.f32 "
        "{%0,%1,%2,%3}, {%4,%5,%6,%7}, {%8,%9}, {%0,%1,%2,%3};"
        : "+f"(c[0]), "+f"(c[1]), "+f"(c[2]), "+f"(c[3])
        : "r"(a[0]), "r"(a[1]), "r"(a[2]), "r"(a[3]), "r"(b0), "r"(b1));
}

// ================= GEMM parameter block (per grid.z) =================
struct GArg {
    const __half *A0;                  // A source 0 (cols [0, K0))
    const __half *A1;                  // A source 1 (cols [K0, K)) or null
    int lda0, lda1, K0, K;
    const __half *Wh, *Wl;             // W [N, K] row-major, fp16 hi/lo
    int ldw;
    const float* bias;
    float* C;                          // fp32 out (if !HOUT)
    __half* Ch;                        // fp16 out (if HOUT)
    int N;
};

// ================= warp-MMA split-fp16 GEMM =================
// C[2048, N] = act( [A0|A1] @ (Wh+Wl)^T + bias ), 2-term: A*Wh + A*Wl, fp32 acc.
// CTA 128x128, 8 warps (4M x 2N), warp tile 32x64, BK=32, 5-stage cp.async, occ 1.
#define LDSW    40                       // smem row stride in fp16 (32 + 8 pad)
#define TSB     (128 * LDSW * 2)         // tile bytes (10240)
#define STAGE_B (3u * TSB)               // A, Wh, Wl (30720 B)
#define NSTAGE  5
#define SMEM_SZ (NSTAGE * STAGE_B)       // 153600 B -> 1 CTA/SM

__device__ __forceinline__ void load_stage(uint32_t sbase, const GArg& g,
                                           int row0, int col0, int kk, int tid)
{
    // resolve A source for this 32-wide chunk (K0 % 32 == 0 guaranteed)
    const __half *ap; int la, ko;
    if (kk < g.K0) { ap = g.A0; la = g.lda0; ko = kk; }
    else           { ap = g.A1; la = g.lda1; ko = kk - g.K0; }

    const int r  = tid >> 2;          // 0..63 (rows; x2 iters)
    const int c4 = tid & 3;           // 16B chunk within 32 cols
#pragma unroll
    for (int i = 0; i < 2; i++) {
        const int rr = i * 64 + r;
        const uint32_t so = (uint32_t)(rr * (LDSW * 2) + c4 * 16);
        cp16(sbase + so,            ap   + (size_t)(row0 + rr) * la    + ko + c4 * 8);
        cp16(sbase + TSB + so,      g.Wh + (size_t)(col0 + rr) * g.ldw + kk + c4 * 8);
        cp16(sbase + 2 * TSB + so,  g.Wl + (size_t)(col0 + rr) * g.ldw + kk + c4 * 8);
    }
}

template <bool RELU, bool HOUT>
__global__ __launch_bounds__(256, 1)
void mma_gemm2(GArg ga, GArg gb)
{
    const GArg g = (blockIdx.z == 0) ? ga : gb;

    extern __shared__ char smem_raw[];
    const uint32_t sb0 = smem_u32(smem_raw);

    const int tid = threadIdx.x;
    const int lane = tid & 31, wid = tid >> 5;
    const int wm = wid & 3, wn = wid >> 2;          // 4 x 2 warp grid
    const int row0 = blockIdx.y * 128, col0 = blockIdx.x * 128;

    float acc[2][8][4];
#pragma unroll
    for (int a = 0; a < 2; a++)
#pragma unroll
        for (int b = 0; b < 8; b++)
#pragma unroll
            for (int c = 0; c < 4; c++) acc[a][b][c] = 0.0f;

    const int NC = g.K / 32;   // min K = 288 -> NC = 9 >= NSTAGE - 1

    // prefetch stages 0..NSTAGE-2
#pragma unroll
    for (int s = 0; s < NSTAGE - 1; s++) {
        load_stage(sb0 + (uint32_t)s * STAGE_B, g, row0, col0, s * 32, tid);
        CP_COMMIT();
    }

    const int lrow = lane & 15;
    const int lcol = (lane >> 4) << 3;

    for (int c = 0; c < NC; c++) {
        CP_WAIT3();            // stage c complete; c+1..c+3 may be in flight
        __syncthreads();

        // prefetch stage c+NSTAGE-1 (buffer consumed at iter c-1; end sync protects)
        const int pf = c + NSTAGE - 1;
        if (pf < NC)
            load_stage(sb0 + (uint32_t)(pf % NSTAGE) * STAGE_B, g, row0, col0, pf * 32, tid);
        CP_COMMIT();

        const uint32_t st = sb0 + (uint32_t)(c % NSTAGE) * STAGE_B;
#pragma unroll
        for (int k16 = 0; k16 < 32; k16 += 16) {
            uint32_t av[2][4], wh[4][4], wl[4][4];
#pragma unroll
            for (int mt = 0; mt < 2; mt++) {
                uint32_t ra = (uint32_t)((wm * 32 + mt * 16 + lrow) * LDSW + k16 + lcol) * 2;
                ldsm4(av[mt], st + ra);
            }
#pragma unroll
            for (int gg = 0; gg < 4; gg++) {
                uint32_t rb = (uint32_t)((wn * 64 + gg * 16 + lrow) * LDSW + k16 + lcol) * 2;
                ldsm4(wh[gg], st + TSB + rb);
                ldsm4(wl[gg], st + 2 * TSB + rb);
            }
#pragma unroll
            for (int mt = 0; mt < 2; mt++)
#pragma unroll
                for (int gg = 0; gg < 4; gg++)
#pragma unroll
                    for (int h = 0; h < 2; h++) {
                        float* cc = acc[mt][gg * 2 + h];
                        mma16816(cc, av[mt], wh[gg][h], wh[gg][h + 2]);
                        mma16816(cc, av[mt], wl[gg][h], wl[gg][h + 2]);
                    }
        }
        __syncthreads();       // stage (c % NSTAGE) free for reuse
    }

    // ---- epilogue ----
    const int gid = lane >> 2, tig = lane & 3;
#pragma unroll
    for (int mt = 0; mt < 2; mt++) {
        const int ra = row0 + wm * 32 + mt * 16 + gid;
#pragma unroll
        for (int nt = 0; nt < 8; nt++) {
            const int col = col0 + wn * 64 + nt * 8 + tig * 2;
            const float b0 = g.bias[col], b1 = g.bias[col + 1];
            const float* cc = acc[mt][nt];
#pragma unroll
            for (int half = 0; half < 2; half++) {
                const int r = ra + half * 8;
                float v0 = cc[half * 2 + 0] + b0;
                float v1 = cc[half * 2 + 1] + b1;
                if (RELU) { v0 = fmaxf(v0, 0.0f); v1 = fmaxf(v1, 0.0f); }
                const size_t o = (size_t)r * g.N + col;
                if (HOUT) {
                    g.Ch[o]     = __float2half_rn(v0);
                    g.Ch[o + 1] = __float2half_rn(v1);
                } else {
                    g.C[o] = v0; g.C[o + 1] = v1;
                }
            }
        }
    }
}

// ================= elementwise kernels =================
// fp32 -> fp16 hi/lo (weights)
__global__ void conv_wsplit(const float* __restrict__ src,
                            __half* __restrict__ hi, __half* __restrict__ lo, int total)
{
    int i = blockIdx.x * blockDim.x + threadIdx.x;
    if (i >= total) return;
    float x = src[i];
    __half h = __float2half_rn(x);
    hi[i] = h;
    lo[i] = __float2half_rn(x - __half2float(h));
}

// fp32 -> fp16 (activations)
__global__ void conv_h(const float* __restrict__ src, __half* __restrict__ dst, int total)
{
    int i = blockIdx.x * blockDim.x + threadIdx.x;
    if (i >= total) return;
    dst[i] = __float2half_rn(src[i]);
}

__global__ void gru_combine(const float* __restrict__ gi, const float* __restrict__ gh,
                            const float* __restrict__ hprev, float* __restrict__ hout,
                            __half* __restrict__ bel_half)
{
    int i = blockIdx.x * blockDim.x + threadIdx.x;
    if (i >= BB * BEL) return;
    int b = i >> 10, c = i & 1023;
    const float* gib = gi + (size_t)b * 3 * BEL;
    const float* ghb = gh + (size_t)b * 3 * BEL;
    float ir = gib[c],           hr = ghb[c];
    float iz = gib[BEL + c],     hz = ghb[BEL + c];
    float in = gib[2 * BEL + c], hn = ghb[2 * BEL + c];
    float r = 1.0f / (1.0f + expf(-(ir + hr)));
    float z = 1.0f / (1.0f + expf(-(iz + hz)));
    float n = tanhf(in + r * hn);
    float h = (1.0f - z) * n + z * hprev[i];
    hout[i] = h;
    bel_half[i] = __float2half_rn(h);
}

// both heads fused; q-half also emits next-step state (fp16)
__global__ void head_epi2(const float* __restrict__ pout, const float* __restrict__ qout,
                          const float* __restrict__ pn, const float* __restrict__ qn,
                          float* __restrict__ o_ps, float* __restrict__ o_pm, float* __restrict__ o_pstd,
                          float* __restrict__ o_qs, float* __restrict__ o_qm, float* __restrict__ o_qstd,
                          __half* __restrict__ st_half)
{
    int i = blockIdx.x * blockDim.x + threadIdx.x;
    if (i >= 2 * BB * SST) return;
    const bool isq = i >= BB * SST;
    const int j = isq ? i - BB * SST : i;
    const int b = j >> 8, c = j & 255;
    const float* src = isq ? qout : pout;
    float m  = src[(size_t)b * 2 * SST + c];
    float lg = src[(size_t)b * 2 * SST + SST + c];
    float y  = expf(lg);
    float sp = (y > 20.0f) ? y : log1pf(expf(y));
    float sd = sp + 0.1f;
    float ns = isq ? qn[j] : pn[j];
    float stv = m + sd * ns;
    if (isq) {
        o_qm[j] = m; o_qstd[j] = sd; o_qs[j] = stv;
        st_half[j] = __float2half_rn(stv);
    } else {
        o_pm[j] = m; o_pstd[j] = sd; o_ps[j] = stv;
    }
}

// ================= host dispatch =================
static inline GArg mk(const __half* A0, int lda0, int K0,
                      const __half* A1, int lda1, int K,
                      const __half* Wh, const __half* Wl, int ldw,
                      const float* bias, int N,
                      float* C, __half* Ch)
{
    GArg g;
    g.A0 = A0; g.A1 = A1;
    g.lda0 = lda0; g.lda1 = lda1; g.K0 = K0; g.K = K;
    g.Wh = Wh; g.Wl = Wl; g.ldw = ldw; g.bias = bias;
    g.C = C; g.Ch = Ch; g.N = N;
    return g;
}

extern "C" void kernel_launch(void* const* d_in, const int* in_sizes, int n_in,
                              void* d_out, int out_size)
{
    const float* prev_state   = (const float*)d_in[0];
    const float* actions      = (const float*)d_in[1];
    const float* prev_belief  = (const float*)d_in[2];
    const float* observations = (const float*)d_in[3];
    const float* prior_noise  = (const float*)d_in[4];
    const float* post_noise   = (const float*)d_in[5];
    const float* W_sa = (const float*)d_in[6];
    const float* b_sa = (const float*)d_in[7];
    const float* W_ih = (const float*)d_in[8];
    const float* W_hh = (const float*)d_in[9];
    const float* b_ih = (const float*)d_in[10];
    const float* b_hh = (const float*)d_in[11];
    const float* W_pb = (const float*)d_in[12];
    const float* b_pb = (const float*)d_in[13];
    const float* W_ps = (const float*)d_in[14];
    const float* b_ps = (const float*)d_in[15];
    const float* W_qb = (const float*)d_in[16];
    const float* b_qb = (const float*)d_in[17];
    const float* W_qs = (const float*)d_in[18];
    const float* b_qs = (const float*)d_in[19];

    float* out = (float*)d_out;
    float* out_bel  = out;
    float* out_ps   = out_bel  + (size_t)TT * BB * BEL;
    float* out_pm   = out_ps   + (size_t)TT * BB * SST;
    float* out_pstd = out_pm   + (size_t)TT * BB * SST;
    float* out_qs   = out_pstd + (size_t)TT * BB * SST;
    float* out_qm   = out_qs   + (size_t)TT * BB * SST;
    float* out_qstd = out_qm   + (size_t)TT * BB * SST;

    cudaFuncSetAttribute(mma_gemm2<true, true>,   cudaFuncAttributeMaxDynamicSharedMemorySize, SMEM_SZ);
    cudaFuncSetAttribute(mma_gemm2<false, false>, cudaFuncAttributeMaxDynamicSharedMemorySize, SMEM_SZ);

    __half *Wsa_h, *Wsa_l, *Wih_h, *Wih_l, *Whh_h, *Whh_l, *Wpb_h, *Wpb_l,
           *Wps_h, *Wps_l, *Wqb_h, *Wqb_l, *Wqs_h, *Wqs_l,
           *act, *obs, *st, *rnn, *bel, *ph, *qh;
    float *gi, *gh, *pout, *qout;
    cudaGetSymbolAddress((void**)&Wsa_h, g_Wsa_h); cudaGetSymbolAddress((void**)&Wsa_l, g_Wsa_l);
    cudaGetSymbolAddress((void**)&Wih_h, g_Wih_h); cudaGetSymbolAddress((void**)&Wih_l, g_Wih_l);
    cudaGetSymbolAddress((void**)&Whh_h, g_Whh_h); cudaGetSymbolAddress((void**)&Whh_l, g_Whh_l);
    cudaGetSymbolAddress((void**)&Wpb_h, g_Wpb_h); cudaGetSymbolAddress((void**)&Wpb_l, g_Wpb_l);
    cudaGetSymbolAddress((void**)&Wps_h, g_Wps_h); cudaGetSymbolAddress((void**)&Wps_l, g_Wps_l);
    cudaGetSymbolAddress((void**)&Wqb_h, g_Wqb_h); cudaGetSymbolAddress((void**)&Wqb_l, g_Wqb_l);
    cudaGetSymbolAddress((void**)&Wqs_h, g_Wqs_h); cudaGetSymbolAddress((void**)&Wqs_l, g_Wqs_l);
    cudaGetSymbolAddress((void**)&act, g_act); cudaGetSymbolAddress((void**)&obs, g_obs);
    cudaGetSymbolAddress((void**)&st,  g_st);  cudaGetSymbolAddress((void**)&rnn, g_rnn);
    cudaGetSymbolAddress((void**)&bel, g_bel); cudaGetSymbolAddress((void**)&ph,  g_ph);
    cudaGetSymbolAddress((void**)&qh,  g_qh);
    cudaGetSymbolAddress((void**)&gi,   g_gi);   cudaGetSymbolAddress((void**)&gh,   g_gh);
    cudaGetSymbolAddress((void**)&pout, g_pout); cudaGetSymbolAddress((void**)&qout, g_qout);

    // ---- one-time conversions (inside graph; replay-deterministic) ----
    auto wconv = [](const float* s, __half* h, __half* l, int total) {
        conv_wsplit<<<(total + 255) / 256, 256>>>(s, h, l, total);
    };
    auto hconv = [](const float* s, __half* d, int total) {
        conv_h<<<(total + 255) / 256, 256>>>(s, d, total);
    };
    wconv(W_sa, Wsa_h, Wsa_l, 1024 * KSA2);
    wconv(W_ih, Wih_h, Wih_l, 3072 * 1024);
    wconv(W_hh, Whh_h, Whh_l, 3072 * 1024);
    wconv(W_pb, Wpb_h, Wpb_l, 1024 * 1024);
    wconv(W_ps, Wps_h, Wps_l,  512 * 1024);
    wconv(W_qb, Wqb_h, Wqb_l, 1024 * 2048);
    wconv(W_qs, Wqs_h, Wqs_l,  512 * 1024);
    hconv(actions,      act, TT * BB * AAC);
    hconv(observations, obs, TT * BB * EMB);
    hconv(prev_state,   st,  BB * SST);
    hconv(prev_belief,  bel, BB * BEL);

    const dim3 g_sa(8, 16, 1), g_gate(24, 16, 2), g_pq(8, 16, 2), g_ss(4, 16, 2);
    const int nb_bel = (BB * BEL) / 256, nb_head2 = (2 * BB * SST) / 256;

    for (int t = 0; t < TT; t++) {
        const __half* a_t = act + (size_t)t * BB * AAC;
        const __half* o_t = obs + (size_t)t * BB * EMB;
        const float* pn_t = prior_noise + (size_t)t * BB * SST;
        const float* qn_t = post_noise  + (size_t)t * BB * SST;
        const float* bel_prev_f32 = (t == 0) ? prev_belief
                                             : out_bel + (size_t)(t - 1) * BB * BEL;
        float* bel_t = out_bel + (size_t)t * BB * BEL;

        // 1. rnn_in = relu([state | action] @ W_sa^T + b_sa) -> fp16
        {
            GArg a = mk(st, SST, SST, a_t, AAC, KSA2,
                        Wsa_h, Wsa_l, KSA2, b_sa, BEL, nullptr, rnn);
            mma_gemm2<true, true><<<g_sa, 256, SMEM_SZ>>>(a, a);
        }
        // 2. GRU gates, batched: z0 gi = rnn@W_ih^T, z1 gh = bel@W_hh^T
        {
            GArg a = mk(rnn, BEL, BEL, nullptr, 0, BEL,
                        Wih_h, Wih_l, BEL, b_ih, 3 * BEL, gi, nullptr);
            GArg b = mk(bel, BEL, BEL, nullptr, 0, BEL,
                        Whh_h, Whh_l, BEL, b_hh, 3 * BEL, gh, nullptr);
            mma_gemm2<false, false><<<g_gate, 256, SMEM_SZ>>>(a, b);
        }
        gru_combine<<<nb_bel, 256>>>(gi, gh, bel_prev_f32, bel_t, bel);

        // 3. hidden heads, batched: z0 ph = relu(bel@W_pb^T), z1 qh = relu([bel|obs]@W_qb^T)
        {
            GArg a = mk(bel, BEL, BEL, nullptr, 0, BEL,
                        Wpb_h, Wpb_l, BEL, b_pb, HID, nullptr, ph);
            GArg b = mk(bel, BEL, BEL, o_t, EMB, BEL + EMB,
                        Wqb_h, Wqb_l, BEL + EMB, b_qb, HID, nullptr, qh);
            mma_gemm2<true, true><<<g_pq, 256, SMEM_SZ>>>(a, b);
        }
        // 4. stat heads, batched: z0 pout = ph@W_ps^T, z1 qout = qh@W_qs^T
        {
            GArg a = mk(ph, HID, HID, nullptr, 0, HID,
                        Wps_h, Wps_l, HID, b_ps, 2 * SST, pout, nullptr);
            GArg b = mk(qh, HID, HID, nullptr, 0, HID,
                        Wqs_h, Wqs_l, HID, b_qs, 2 * SST, qout, nullptr);
            mma_gemm2<false, false><<<g_ss, 256, SMEM_SZ>>>(a, b);
        }
        // 5. both head epilogues + next-step state
        head_epi2<<<nb_head2, 256>>>(pout, qout, pn_t, qn_t,
                                     out_ps   + (size_t)t * BB * SST,
                                     out_pm   + (size_t)t * BB * SST,
                                     out_pstd + (size_t)t * BB * SST,
                                     out_qs   + (size_t)t * BB * SST,
                                     out_qm   + (size_t)t * BB * SST,
                                     out_qstd + (size_t)t * BB * SST,
                                     st);
    }
}